// round 6
// baseline (speedup 1.0000x reference)
#include <cuda_runtime.h>
#include <math.h>

#define IMG 512
#define BS  32
#define OH  255
#define OW  255
#define TC  16
#define NP  17
#define SIMW 18

typedef unsigned long long ull;

// packed/pre-scaled weights (see prep_kernel layout)
__constant__ __align__(8) float cbuf[172];
__device__ __align__(8) float g_stage[172];

// Layout (float offsets):
//   0: W1p  (32 float2) [p*4+j] = (W1[2p][j],   W1[2p+1][j])
//  64: b1p  ( 4 float2) [j]     = (b1[j], 0)
//  72: W2s  (16 float ) 0.5*W2
//  88: b2   ( 4 float )
//  92: W3p  (32 float2) [j*8+i] = 0.5*(W3[j][2i], W3[j][2i+1])
// 156: b3p  ( 8 float2) [i]     = (b3[2i], b3[2i+1])
__global__ void prep_kernel(const float* __restrict__ W1, const float* __restrict__ b1,
                            const float* __restrict__ W2, const float* __restrict__ b2,
                            const float* __restrict__ W3, const float* __restrict__ b3) {
    int f = threadIdx.x;
    if (f >= 172) return;
    float v;
    if (f < 64) {
        int q = f >> 1, lane = f & 1;
        int p = q >> 2, j = q & 3;
        v = W1[(2 * p + lane) * 4 + j];
    } else if (f < 72) {
        int q = (f - 64) >> 1, lane = f & 1;
        v = lane ? 0.0f : b1[q];
    } else if (f < 88) {
        v = 0.5f * W2[f - 72];
    } else if (f < 92) {
        v = b2[f - 88];
    } else if (f < 156) {
        int q = (f - 92) >> 1, lane = f & 1;
        int j = q >> 3, i = q & 7;
        v = 0.5f * W3[j * 16 + 2 * i + lane];
    } else {
        int q = (f - 156) >> 1, lane = f & 1;
        v = b3[2 * q + lane];
    }
    g_stage[f] = v;
}

__device__ __forceinline__ ull pk(float lo, float hi) {
    ull r; asm("mov.b64 %0, {%1, %2};" : "=l"(r) : "f"(lo), "f"(hi)); return r;
}
__device__ __forceinline__ void upk(ull v, float& lo, float& hi) {
    asm("mov.b64 {%0, %1}, %2;" : "=f"(lo), "=f"(hi) : "l"(v));
}
__device__ __forceinline__ ull fma2(ull a, ull b, ull c) {
    ull d; asm("fma.rn.f32x2 %0, %1, %2, %3;" : "=l"(d) : "l"(a), "l"(b), "l"(c)); return d;
}
__device__ __forceinline__ ull add2(ull a, ull b) {
    ull d; asm("add.rn.f32x2 %0, %1, %2;" : "=l"(d) : "l"(a), "l"(b)); return d;
}

__global__ __launch_bounds__(256, 4)
void fused_kernel(const float* __restrict__ img, float* __restrict__ out) {
    __shared__ float sim[NP * SIMW];

    const int t  = threadIdx.x;
    const int b0 = blockIdx.x * TC;
    const int a0 = blockIdx.y * TC;
    const int bt = blockIdx.z;
    const float* imgb = img + (size_t)bt * (IMG * IMG);

    const ull* W1p = reinterpret_cast<const ull*>(cbuf);
    const ull* b1p = reinterpret_cast<const ull*>(cbuf + 64);
    const float* W2s = cbuf + 72;
    const float* b2  = cbuf + 88;
    const ull* W3p = reinterpret_cast<const ull*>(cbuf + 92);
    const ull* b3p = reinterpret_cast<const ull*>(cbuf + 156);

    // ---- patch phase: 17x17 patches, direct global gather (L1/L2-cached)
    for (int p = t; p < NP * NP; p += 256) {
        int py = p / NP;
        int px = p - py * NP;
        int oy = a0 - 1 + py;
        int ox = b0 - 1 + px;
        float s = 0.0f;
        if ((unsigned)oy < OH && (unsigned)ox < OW) {
            const float* base = imgb + (size_t)(2 * oy) * IMG + 2 * ox;
            ull xp[8];                       // natural lane pairs (x_{2k}, x_{2k+1})
#pragma unroll
            for (int r = 0; r < 4; r++) {
                float2 v0 = __ldg(reinterpret_cast<const float2*>(base + (size_t)r * IMG));
                float2 v1 = __ldg(reinterpret_cast<const float2*>(base + (size_t)r * IMG + 2));
                xp[2 * r]     = pk(v0.x, v0.y);
                xp[2 * r + 1] = pk(v1.x, v1.y);
            }

            // layer 1: packed over input pairs, horizontal reduce, relu=v+|v| (2x)
            ull acc[4];
#pragma unroll
            for (int j = 0; j < 4; j++) acc[j] = b1p[j];   // (b1,0)
#pragma unroll
            for (int q = 0; q < 8; q++)
#pragma unroll
                for (int j = 0; j < 4; j++) acc[j] = fma2(xp[q], W1p[q * 4 + j], acc[j]);
            float h[4];
#pragma unroll
            for (int j = 0; j < 4; j++) {
                float lo, hi; upk(acc[j], lo, hi);
                float hv = lo + hi;
                h[j] = hv + fabsf(hv);                      // 2*relu, W2 pre-scaled
            }

            // layer 2: scalar 4->4 (W2s = 0.5*W2), relu (2x, W3 pre-scaled)
            float g[4];
#pragma unroll
            for (int j = 0; j < 4; j++) g[j] = b2[j];
#pragma unroll
            for (int i = 0; i < 4; i++)
#pragma unroll
                for (int j = 0; j < 4; j++) g[j] = fmaf(h[i], W2s[i * 4 + j], g[j]);
            ull gb[4];
#pragma unroll
            for (int j = 0; j < 4; j++) {
                float gv = g[j] + fabsf(g[j]);
                gb[j] = pk(gv, gv);
            }

            // layer 3: packed over output pairs (W3p = 0.5*W3)
            ull yp[8];
#pragma unroll
            for (int i = 0; i < 8; i++) yp[i] = b3p[i];
#pragma unroll
            for (int j = 0; j < 4; j++)
#pragma unroll
                for (int i = 0; i < 8; i++) yp[i] = fma2(gb[j], W3p[j * 8 + i], yp[i]);
            // packed relu: y + |y|  (abs via ALU-pipe LOP3)
#pragma unroll
            for (int i = 0; i < 8; i++)
                yp[i] = add2(yp[i], yp[i] & 0x7FFFFFFF7FFFFFFFULL);

            // packed cosine accumulation
            ull d2 = 0ULL, nxp = 0ULL, nyp = 0ULL;
#pragma unroll
            for (int i = 0; i < 8; i++) {
                d2  = fma2(xp[i], yp[i], d2);    // = 2*dot
                nxp = fma2(xp[i], xp[i], nxp);
                nyp = fma2(yp[i], yp[i], nyp);   // = 4*ny2
            }
            float dl, dh, xl, xh, yl, yh;
            upk(d2, dl, dh); upk(nxp, xl, xh); upk(nyp, yl, yh);
            float dot = dl + dh, nx2 = xl + xh, ny2 = yl + yh;
            // scale factors cancel; clamps: nx2@1e-16, (4*ny2)@4e-16
            s = dot * rsqrtf(fmaxf(nx2, 1e-16f)) * rsqrtf(fmaxf(ny2, 4e-16f));
        }
        sim[py * SIMW + px] = s;
    }
    __syncthreads();

    // ---- fold: thread -> one cell (a,b) -> 2x2 identical output pixels
    const int tx = t & 15;
    const int ty = t >> 4;
    const int a = a0 + ty;
    const int b = b0 + tx;

    const float* s0 = sim + ty * SIMW + tx;
    float sum = (s0[0] + s0[1]) + (s0[SIMW] + s0[SIMW + 1]);
    float invy = (a == 0 || a == 255) ? 1.0f : 0.5f;
    float invx = (b == 0 || b == 255) ? 1.0f : 0.5f;
    float v = sum * (invy * invx);

    float2 vv = make_float2(v, v);
    float* op = out + (size_t)bt * (IMG * IMG) + (size_t)(2 * a) * IMG + 2 * b;
    *reinterpret_cast<float2*>(op) = vv;
    *reinterpret_cast<float2*>(op + IMG) = vv;
}

extern "C" void kernel_launch(void* const* d_in, const int* in_sizes, int n_in,
                              void* d_out, int out_size) {
    const float* img = (const float*)d_in[0];
    float* out = (float*)d_out;

    prep_kernel<<<1, 192>>>((const float*)d_in[1], (const float*)d_in[2],
                            (const float*)d_in[3], (const float*)d_in[4],
                            (const float*)d_in[5], (const float*)d_in[6]);
    void* src = nullptr;
    cudaGetSymbolAddress(&src, g_stage);
    cudaMemcpyToSymbolAsync(cbuf, src, 172 * sizeof(float), 0, cudaMemcpyDeviceToDevice);

    dim3 grid(IMG / (2 * TC), IMG / (2 * TC), BS);   // 16 x 16 x 32
    fused_kernel<<<grid, 256>>>(img, out);
}

// round 7
// speedup vs baseline: 1.2677x; 1.2677x over previous
#include <cuda_runtime.h>
#include <math.h>

#define IMG 512
#define BS  32
#define OH  255
#define OW  255
#define TC  32     // cells per tile dim (tile = 64x64 output pixels)
#define NP  33     // patches per tile dim
#define SIMW 34    // padded sim row stride

typedef unsigned long long ull;

// packed/pre-scaled weights (layout below)
__constant__ __align__(8) float cbuf[172];
__device__ __align__(8) float g_stage[172];

// Layout (float offsets):
//   0: W1p  (32 float2) [p*4+j] = (W1[2p][j],   W1[2p+1][j])
//  64: b1p  ( 4 float2) [j]     = (b1[j], 0)
//  72: W2s  (16 float ) 0.5*W2
//  88: b2   ( 4 float )
//  92: W3p  (32 float2) [j*8+i] = 0.5*(W3[j][2i], W3[j][2i+1])
// 156: b3p  ( 8 float2) [i]     = (b3[2i], b3[2i+1])
__global__ void prep_kernel(const float* __restrict__ W1, const float* __restrict__ b1,
                            const float* __restrict__ W2, const float* __restrict__ b2,
                            const float* __restrict__ W3, const float* __restrict__ b3) {
    int f = threadIdx.x;
    if (f >= 172) return;
    float v;
    if (f < 64) {
        int q = f >> 1, lane = f & 1;
        int p = q >> 2, j = q & 3;
        v = W1[(2 * p + lane) * 4 + j];
    } else if (f < 72) {
        int q = (f - 64) >> 1, lane = f & 1;
        v = lane ? 0.0f : b1[q];
    } else if (f < 88) {
        v = 0.5f * W2[f - 72];
    } else if (f < 92) {
        v = b2[f - 88];
    } else if (f < 156) {
        int q = (f - 92) >> 1, lane = f & 1;
        int j = q >> 3, i = q & 7;
        v = 0.5f * W3[j * 16 + 2 * i + lane];
    } else {
        int q = (f - 156) >> 1, lane = f & 1;
        v = b3[2 * q + lane];
    }
    g_stage[f] = v;
}

__device__ __forceinline__ ull pk(float lo, float hi) {
    ull r; asm("mov.b64 %0, {%1, %2};" : "=l"(r) : "f"(lo), "f"(hi)); return r;
}
__device__ __forceinline__ void upk(ull v, float& lo, float& hi) {
    asm("mov.b64 {%0, %1}, %2;" : "=f"(lo), "=f"(hi) : "l"(v));
}
__device__ __forceinline__ ull fma2(ull a, ull b, ull c) {
    ull d; asm("fma.rn.f32x2 %0, %1, %2, %3;" : "=l"(d) : "l"(a), "l"(b), "l"(c)); return d;
}
__device__ __forceinline__ ull add2(ull a, ull b) {
    ull d; asm("add.rn.f32x2 %0, %1, %2;" : "=l"(d) : "l"(a), "l"(b)); return d;
}

__global__ __launch_bounds__(256, 4)
void fused_kernel(const float* __restrict__ img, float* __restrict__ out) {
    __shared__ float sim[NP * SIMW];

    const int t  = threadIdx.x;
    const int b0 = blockIdx.x * TC;
    const int a0 = blockIdx.y * TC;
    const int bt = blockIdx.z;
    const float* imgb = img + (size_t)bt * (IMG * IMG);

    const ull* W1p = reinterpret_cast<const ull*>(cbuf);
    const ull* b1p = reinterpret_cast<const ull*>(cbuf + 64);
    const float* W2s = cbuf + 72;
    const float* b2  = cbuf + 88;
    const ull* W3p = reinterpret_cast<const ull*>(cbuf + 92);
    const ull* b3p = reinterpret_cast<const ull*>(cbuf + 156);

    // ---- patch phase: 33x33 patches, direct global gather (L1/L2-cached)
    for (int p = t; p < NP * NP; p += 256) {
        int py = p / NP;
        int px = p - py * NP;
        int oy = a0 - 1 + py;
        int ox = b0 - 1 + px;
        float s = 0.0f;
        if ((unsigned)oy < OH && (unsigned)ox < OW) {
            const float* base = imgb + (size_t)(2 * oy) * IMG + 2 * ox;
            ull xp[8];            // natural lane pairs (x_{2k}, x_{2k+1})
            ull nxp = 0ULL;       // nx2 accumulated during load
#pragma unroll
            for (int r = 0; r < 4; r++) {
                float2 v0 = __ldg(reinterpret_cast<const float2*>(base + (size_t)r * IMG));
                float2 v1 = __ldg(reinterpret_cast<const float2*>(base + (size_t)r * IMG + 2));
                xp[2 * r]     = pk(v0.x, v0.y);
                xp[2 * r + 1] = pk(v1.x, v1.y);
                nxp = fma2(xp[2 * r], xp[2 * r], nxp);
                nxp = fma2(xp[2 * r + 1], xp[2 * r + 1], nxp);
            }

            // layer 1: packed over input pairs, horizontal reduce, relu=v+|v| (2x)
            ull acc[4];
#pragma unroll
            for (int j = 0; j < 4; j++) acc[j] = b1p[j];   // (b1,0)
#pragma unroll
            for (int q = 0; q < 8; q++)
#pragma unroll
                for (int j = 0; j < 4; j++) acc[j] = fma2(xp[q], W1p[q * 4 + j], acc[j]);
            float h[4];
#pragma unroll
            for (int j = 0; j < 4; j++) {
                float lo, hi; upk(acc[j], lo, hi);
                float hv = lo + hi;
                h[j] = hv + fabsf(hv);                      // 2*relu, W2 pre-scaled
            }

            // layer 2: scalar 4->4 (W2s = 0.5*W2), relu (2x, W3 pre-scaled)
            float g[4];
#pragma unroll
            for (int j = 0; j < 4; j++) g[j] = b2[j];
#pragma unroll
            for (int i = 0; i < 4; i++)
#pragma unroll
                for (int j = 0; j < 4; j++) g[j] = fmaf(h[i], W2s[i * 4 + j], g[j]);
            ull gb[4];
#pragma unroll
            for (int j = 0; j < 4; j++) {
                float gv = g[j] + fabsf(g[j]);
                gb[j] = pk(gv, gv);
            }

            // layer 3 fused with cosine: per output pair, compute y, relu,
            // accumulate dot/ny2 immediately (no yp[] array -> low reg pressure)
            ull d2 = 0ULL, nyp = 0ULL;
#pragma unroll
            for (int i = 0; i < 8; i++) {
                ull y = b3p[i];
#pragma unroll
                for (int j = 0; j < 4; j++) y = fma2(gb[j], W3p[j * 8 + i], y);
                y = add2(y, y & 0x7FFFFFFF7FFFFFFFULL);   // 2*relu(y)
                d2  = fma2(xp[i], y, d2);                 // = 2*dot
                nyp = fma2(y, y, nyp);                    // = 4*ny2
            }
            float dl, dh, xl, xh, yl, yh;
            upk(d2, dl, dh); upk(nxp, xl, xh); upk(nyp, yl, yh);
            float dot = dl + dh, nx2 = xl + xh, ny2 = yl + yh;
            // scale factors cancel; clamps: nx2@1e-16, (4*ny2)@4e-16
            s = dot * rsqrtf(fmaxf(nx2, 1e-16f)) * rsqrtf(fmaxf(ny2, 4e-16f));
        }
        sim[py * SIMW + px] = s;
    }
    __syncthreads();

    // ---- fold: each thread handles 2x2 cells -> 4x4 output pixels
    const int tx = t & 15;
    const int ty = t >> 4;
    float* outb = out + (size_t)bt * (IMG * IMG);
#pragma unroll
    for (int dy = 0; dy < 2; dy++) {
        int ca = 2 * ty + dy;          // local cell row 0..31
        int a  = a0 + ca;              // global cell row 0..255
        int cb = 2 * tx;               // local cell col (left of pair)
        const float* s0 = sim + ca * SIMW + cb;
        const float* s1 = s0 + SIMW;
        float p00 = s0[0], p01 = s0[1], p02 = s0[2];
        float p10 = s1[0], p11 = s1[1], p12 = s1[2];
        float sumL = (p00 + p01) + (p10 + p11);
        float sumR = (p01 + p02) + (p11 + p12);
        int bL = b0 + cb, bR = bL + 1;
        float invy = (a == 0 || a == 255) ? 1.0f : 0.5f;
        float invL = (bL == 0 || bL == 255) ? 1.0f : 0.5f;
        float invR = (bR == 255) ? 1.0f : 0.5f;
        float vL = sumL * (invy * invL);
        float vR = sumR * (invy * invR);
        float4 v4 = make_float4(vL, vL, vR, vR);
        float* op = outb + (size_t)(2 * a) * IMG + 2 * bL;
        *reinterpret_cast<float4*>(op) = v4;
        *reinterpret_cast<float4*>(op + IMG) = v4;
    }
}

extern "C" void kernel_launch(void* const* d_in, const int* in_sizes, int n_in,
                              void* d_out, int out_size) {
    const float* img = (const float*)d_in[0];
    float* out = (float*)d_out;

    prep_kernel<<<1, 192>>>((const float*)d_in[1], (const float*)d_in[2],
                            (const float*)d_in[3], (const float*)d_in[4],
                            (const float*)d_in[5], (const float*)d_in[6]);
    void* src = nullptr;
    cudaGetSymbolAddress(&src, g_stage);
    cudaMemcpyToSymbolAsync(cbuf, src, 172 * sizeof(float), 0, cudaMemcpyDeviceToDevice);

    dim3 grid(IMG / (2 * TC), IMG / (2 * TC), BS);   // 8 x 8 x 32
    fused_kernel<<<grid, 256>>>(img, out);
}